// round 15
// baseline (speedup 1.0000x reference)
#include <cuda_runtime.h>
#include <stdint.h>

// BinarizedLinear: act[d,o] = sum_i W[d,o,i]*x[d,i]; out[d,o] = (act > bias[d,o]) ? 1 : 0
// D=64, OUT=2048, IN=2048.
//
// FINAL. Exact-bound skip kernel at the harness replay floor (6.62-6.66us wall
// across four consecutive rounds; ncu kernel times 4.4-6.2us are fully hidden
// under replay overhead -> no kernel-internal change can move the benchmark).
// Session: 147.0us HBM-roofline stream (92.9% DRAM-active, 7.37 TB/s) -> 6.6us (22x).
//
//   Bound (exact for any 0/1 W,x): act[d,o] <= count[d] = sum_i x[d,i].
//   count <= bias  =>  out = 0 with zero weight-row reads.
//   Per-warp autonomous count: 16 back-to-back LDG.128 over the L2-hot x row,
//   dual accumulators, 5-shfl butterfly; no smem, no barriers. Prologue
//   (zero-store + bias load) is cnt-independent and issues under the x-load
//   latency. Any row with count > bias is computed exactly by the warp using
//   the measured-optimal R2 stream (16 outstanding LDG.128, 93% DRAM-active),
//   so worst-case inputs remain correct at streaming speed.

#define D_DIRS 64
#define OUT_F  2048
#define IN_F   2048
#define THREADS 128                        // 4 warps, 4 outputs per thread
#define BLOCKS_PER_D 4                     // 512 outputs per block
#define BLOCKS  (D_DIRS * BLOCKS_PER_D)    // 256 CTAs

__global__ __launch_bounds__(THREADS)
void binlin_fused(const float* __restrict__ W,
                  const float* __restrict__ x,
                  const float* __restrict__ bias,
                  float* __restrict__ out)
{
    const int d     = blockIdx.x >> 2;
    const int obase = (blockIdx.x & 3) << 9;    // 0/512/1024/1536
    const int lane  = threadIdx.x & 31;

    // Each thread owns 4 consecutive outputs (float4-aligned). Zero-store and
    // bias load are cnt-independent: issue them before the count so they
    // overlap the x-load round trip.
    const int o0   = obase + threadIdx.x * 4;
    const int idx0 = d * OUT_F + o0;

    float4 z; z.x = z.y = z.z = z.w = 0.0f;
    ((float4*)out)[idx0 >> 2] = z;
    const float4 b4 = __ldg((const float4*)bias + (idx0 >> 2));

    // Warp-autonomous count[d]: 16 back-to-back LDG.128 per lane (L2-hot x),
    // dual accumulators to halve the exposed FADD chain, 5-shfl butterfly.
    const float4* __restrict__ xr = (const float4*)x + (size_t)d * (IN_F / 4);
    float s0 = 0.0f, s1 = 0.0f;
    #pragma unroll
    for (int it = 0; it < 16; it += 2) {
        float4 v0 = __ldg(&xr[it * 32 + lane]);
        float4 v1 = __ldg(&xr[(it + 1) * 32 + lane]);
        s0 += (v0.x + v0.y) + (v0.z + v0.w);
        s1 += (v1.x + v1.y) + (v1.z + v1.w);
    }
    float s = s0 + s1;
    #pragma unroll
    for (int off = 16; off > 0; off >>= 1)
        s += __shfl_xor_sync(0xFFFFFFFFu, s, off);
    const float cnt = s;                        // identical in all lanes

    unsigned flags = 0;
    if (cnt > b4.x) flags |= 1u;
    if (cnt > b4.y) flags |= 2u;
    if (cnt > b4.z) flags |= 4u;
    if (cnt > b4.w) flags |= 8u;

    // Exact fallback: warp cooperatively computes any row where count > bias,
    // overwriting that row's zero (same-thread program order keeps it safe).
    unsigned m = __ballot_sync(0xFFFFFFFFu, flags != 0);
    while (m) {
        const int src = __ffs(m) - 1;
        m &= m - 1u;
        const unsigned f     = __shfl_sync(0xFFFFFFFFu, flags, src);
        const int      sidx0 = __shfl_sync(0xFFFFFFFFu, idx0, src);

        #pragma unroll
        for (int j = 0; j < 4; ++j) {
            if (!(f & (1u << j))) continue;
            const int row = sidx0 + j;
            const float4* __restrict__ wr =
                (const float4*)W + (size_t)row * (IN_F / 4);

            float acc = 0.0f;
            #pragma unroll
            for (int it = 0; it < 16; ++it) {
                float4 w  = __ldg(&wr[it * 32 + lane]);
                float4 xv = __ldg(&xr[it * 32 + lane]);   // L2-resident
                acc = fmaf(w.x, xv.x, acc);
                acc = fmaf(w.y, xv.y, acc);
                acc = fmaf(w.z, xv.z, acc);
                acc = fmaf(w.w, xv.w, acc);
            }
            #pragma unroll
            for (int off = 16; off > 0; off >>= 1)
                acc += __shfl_xor_sync(0xFFFFFFFFu, acc, off);

            if (lane == src) {
                const float bv = (j == 0) ? b4.x : (j == 1) ? b4.y
                               : (j == 2) ? b4.z : b4.w;
                out[row] = (acc > bv) ? 1.0f : 0.0f;
            }
        }
    }
}

extern "C" void kernel_launch(void* const* d_in, const int* in_sizes, int n_in,
                              void* d_out, int out_size)
{
    const float* W    = (const float*)d_in[0];
    const float* x    = (const float*)d_in[1];
    const float* bias = (const float*)d_in[2];
    float*       out  = (float*)d_out;

    binlin_fused<<<BLOCKS, THREADS>>>(W, x, bias, out);   // 256 CTAs, 1 launch
}

// round 16
// speedup vs baseline: 1.0048x; 1.0048x over previous
#include <cuda_runtime.h>
#include <stdint.h>

// BinarizedLinear: act[d,o] = sum_i W[d,o,i]*x[d,i]; out[d,o] = (act > bias[d,o]) ? 1 : 0
// D=64, OUT=2048, IN=2048.
//
// FINAL (verified across 5 consecutive rounds at 6.62-6.66us wall = harness
// graph-replay floor; ncu kernel times 4.4-6.2us fully hidden beneath it).
// Session: 147.0us HBM-roofline stream (92.9% DRAM-active, 7.37 TB/s) -> 6.6us (22x).
//
//   Bound (exact for any 0/1 W,x): act[d,o] <= count[d] = sum_i x[d,i].
//   count <= bias  =>  out = 0 with zero weight-row reads.
//   Per-warp autonomous count: 16 back-to-back LDG.128 over the L2-hot x row,
//   dual accumulators, 5-shfl butterfly; no smem, no barriers. Prologue
//   (zero-store + bias load) is cnt-independent and issues under the x-load
//   latency. Any row with count > bias is computed exactly by the warp using
//   the measured-optimal R2 stream (16 outstanding LDG.128, 93% DRAM-active),
//   so worst-case inputs remain correct at streaming speed.

#define D_DIRS 64
#define OUT_F  2048
#define IN_F   2048
#define THREADS 128                        // 4 warps, 4 outputs per thread
#define BLOCKS_PER_D 4                     // 512 outputs per block
#define BLOCKS  (D_DIRS * BLOCKS_PER_D)    // 256 CTAs

__global__ __launch_bounds__(THREADS)
void binlin_fused(const float* __restrict__ W,
                  const float* __restrict__ x,
                  const float* __restrict__ bias,
                  float* __restrict__ out)
{
    const int d     = blockIdx.x >> 2;
    const int obase = (blockIdx.x & 3) << 9;    // 0/512/1024/1536
    const int lane  = threadIdx.x & 31;

    // Each thread owns 4 consecutive outputs (float4-aligned). Zero-store and
    // bias load are cnt-independent: issue them before the count so they
    // overlap the x-load round trip.
    const int o0   = obase + threadIdx.x * 4;
    const int idx0 = d * OUT_F + o0;

    float4 z; z.x = z.y = z.z = z.w = 0.0f;
    ((float4*)out)[idx0 >> 2] = z;
    const float4 b4 = __ldg((const float4*)bias + (idx0 >> 2));

    // Warp-autonomous count[d]: 16 back-to-back LDG.128 per lane (L2-hot x),
    // dual accumulators to halve the exposed FADD chain, 5-shfl butterfly.
    const float4* __restrict__ xr = (const float4*)x + (size_t)d * (IN_F / 4);
    float s0 = 0.0f, s1 = 0.0f;
    #pragma unroll
    for (int it = 0; it < 16; it += 2) {
        float4 v0 = __ldg(&xr[it * 32 + lane]);
        float4 v1 = __ldg(&xr[(it + 1) * 32 + lane]);
        s0 += (v0.x + v0.y) + (v0.z + v0.w);
        s1 += (v1.x + v1.y) + (v1.z + v1.w);
    }
    float s = s0 + s1;
    #pragma unroll
    for (int off = 16; off > 0; off >>= 1)
        s += __shfl_xor_sync(0xFFFFFFFFu, s, off);
    const float cnt = s;                        // identical in all lanes

    unsigned flags = 0;
    if (cnt > b4.x) flags |= 1u;
    if (cnt > b4.y) flags |= 2u;
    if (cnt > b4.z) flags |= 4u;
    if (cnt > b4.w) flags |= 8u;

    // Exact fallback: warp cooperatively computes any row where count > bias,
    // overwriting that row's zero (same-thread program order keeps it safe).
    unsigned m = __ballot_sync(0xFFFFFFFFu, flags != 0);
    while (m) {
        const int src = __ffs(m) - 1;
        m &= m - 1u;
        const unsigned f     = __shfl_sync(0xFFFFFFFFu, flags, src);
        const int      sidx0 = __shfl_sync(0xFFFFFFFFu, idx0, src);

        #pragma unroll
        for (int j = 0; j < 4; ++j) {
            if (!(f & (1u << j))) continue;
            const int row = sidx0 + j;
            const float4* __restrict__ wr =
                (const float4*)W + (size_t)row * (IN_F / 4);

            float acc = 0.0f;
            #pragma unroll
            for (int it = 0; it < 16; ++it) {
                float4 w  = __ldg(&wr[it * 32 + lane]);
                float4 xv = __ldg(&xr[it * 32 + lane]);   // L2-resident
                acc = fmaf(w.x, xv.x, acc);
                acc = fmaf(w.y, xv.y, acc);
                acc = fmaf(w.z, xv.z, acc);
                acc = fmaf(w.w, xv.w, acc);
            }
            #pragma unroll
            for (int off = 16; off > 0; off >>= 1)
                acc += __shfl_xor_sync(0xFFFFFFFFu, acc, off);

            if (lane == src) {
                const float bv = (j == 0) ? b4.x : (j == 1) ? b4.y
                               : (j == 2) ? b4.z : b4.w;
                out[row] = (acc > bv) ? 1.0f : 0.0f;
            }
        }
    }
}

extern "C" void kernel_launch(void* const* d_in, const int* in_sizes, int n_in,
                              void* d_out, int out_size)
{
    const float* W    = (const float*)d_in[0];
    const float* x    = (const float*)d_in[1];
    const float* bias = (const float*)d_in[2];
    float*       out  = (float*)d_out;

    binlin_fused<<<BLOCKS, THREADS>>>(W, x, bias, out);   // 256 CTAs, 1 launch
}